// round 1
// baseline (speedup 1.0000x reference)
#include <cuda_runtime.h>
#include <math.h>

// Problem dims
#define B   128
#define T   64
#define X   64
#define H   512
#define D   512
#define Z   64
#define KF  2
#define G   1536          // 3*H
#define BT  8192          // B*T
#define S   524288        // B*T*64 (per-tensor output elems)

// ---------------- scratch (device globals; no allocation) ----------------
__device__ float  g_xT[BT * X];            // x rearranged to [t*B+b][X]
__device__ float  g_gi[BT * G];            // gi for enc, reused for dec
__device__ float  g_h[(T + 1) * B * H];    // h_all, slot 0 = zeros
__device__ float  g_phi[BT * D];           // phi, reused enc/dec
__device__ float  g_head[BT * 128];        // head pre-activations (mean|std)
__device__ float  g_z[BT * Z];             // z in [t*B+b][Z] layout
__device__ double g_part[512];             // reduction partials (256 blocks x 2)

// ---------------- helpers ----------------
__device__ __forceinline__ float sigmoidf_(float v) {
    return 1.0f / (1.0f + expf(-v));
}
__device__ __forceinline__ float softplusf_(float v) {
    return (v > 20.0f) ? v : log1pf(expf(v));
}

// ---------------- kernel: rearrange x [B,T,X] -> [t*B+b][X] ----------------
__global__ void k_transpose_x(const float* __restrict__ x, float* __restrict__ xT) {
    int i = blockIdx.x * blockDim.x + threadIdx.x;
    if (i < B * T * X) {
        int b = i >> 12;            // / (T*X)=4096
        int r = i & 4095;
        int t = r >> 6;
        int xi = r & 63;
        xT[((t << 7) + b) * X + xi] = x[i];
    }
}

// ---------------- kernel: zero a buffer ----------------
__global__ void k_zero(float* __restrict__ p, int n) {
    int i = blockIdx.x * blockDim.x + threadIdx.x;
    if (i < n) p[i] = 0.0f;
}

// ---------------- generic tiled GEMM: C[m][n] = act(sum_k A[m][k]*W[n][k] + bias[n])
// TM=64, TN=64, TK=32, 256 threads, 4x4 per thread. All dims divide tiles.
__global__ void k_gemm(const float* __restrict__ A, int lda,
                       const float* __restrict__ W, int ldw,
                       const float* __restrict__ bias,
                       float* __restrict__ C, int ldc,
                       int K, int act) {
    __shared__ float As[32][65];  // [k][m]
    __shared__ float Ws[32][65];  // [k][n]
    const int m0 = blockIdx.x * 64;
    const int n0 = blockIdx.y * 64;
    const int tx = threadIdx.x & 15;
    const int ty = threadIdx.x >> 4;
    float acc[4][4] = {{0.f}};

    for (int k0 = 0; k0 < K; k0 += 32) {
        #pragma unroll
        for (int i = threadIdx.x; i < 64 * 32; i += 256) {
            int k = i & 31, m = i >> 5;
            As[k][m] = A[(size_t)(m0 + m) * lda + k0 + k];
        }
        #pragma unroll
        for (int i = threadIdx.x; i < 64 * 32; i += 256) {
            int k = i & 31, n = i >> 5;
            Ws[k][n] = W[(size_t)(n0 + n) * ldw + k0 + k];
        }
        __syncthreads();
        #pragma unroll
        for (int k = 0; k < 32; k++) {
            float a[4], bv[4];
            #pragma unroll
            for (int i = 0; i < 4; i++) a[i] = As[k][ty + 16 * i];
            #pragma unroll
            for (int j = 0; j < 4; j++) bv[j] = Ws[k][tx + 16 * j];
            #pragma unroll
            for (int i = 0; i < 4; i++)
                #pragma unroll
                for (int j = 0; j < 4; j++)
                    acc[i][j] += a[i] * bv[j];
        }
        __syncthreads();
    }
    #pragma unroll
    for (int i = 0; i < 4; i++) {
        int m = m0 + ty + 16 * i;
        #pragma unroll
        for (int j = 0; j < 4; j++) {
            int n = n0 + tx + 16 * j;
            float v = acc[i][j] + bias[n];
            if (act == 1) v = fmaxf(v, 0.0f);
            C[(size_t)m * ldc + n] = v;
        }
    }
}

// ---------------- fused GRU step: gh = h@Wh.T + bh, then gates, write h_next
// grid (B/16, H/32) = (8,16), 128 threads. Each thread: 2b x 2j x 3 gates.
__global__ void k_gru_step(const float* __restrict__ gi,     // [B,1536] for this t
                           const float* __restrict__ hprev,  // [B,512]
                           const float* __restrict__ Wh,     // [1536,512]
                           const float* __restrict__ bh,     // [1536]
                           float* __restrict__ hnext) {      // [B,512]
    __shared__ float hs[32][17];       // [k][b]
    __shared__ float ws[3][32][33];    // [g][k][j]
    const int b0 = blockIdx.x * 16;
    const int j0 = blockIdx.y * 32;
    const int tx = threadIdx.x & 15;   // j group
    const int ty = threadIdx.x >> 4;   // 0..7 b group
    float acc[3][2][2] = {{{0.f}}};

    for (int k0 = 0; k0 < H; k0 += 32) {
        #pragma unroll
        for (int i = threadIdx.x; i < 16 * 32; i += 128) {
            int k = i & 31, b = i >> 5;
            hs[k][b] = hprev[(b0 + b) * H + k0 + k];
        }
        #pragma unroll
        for (int i = threadIdx.x; i < 3 * 32 * 32; i += 128) {
            int k = i & 31, j = (i >> 5) & 31, g = i >> 10;
            ws[g][k][j] = Wh[(size_t)(g * H + j0 + j) * H + k0 + k];
        }
        __syncthreads();
        #pragma unroll
        for (int k = 0; k < 32; k++) {
            float h0v = hs[k][ty];
            float h1v = hs[k][ty + 8];
            #pragma unroll
            for (int g = 0; g < 3; g++) {
                float w0 = ws[g][k][tx];
                float w1 = ws[g][k][tx + 16];
                acc[g][0][0] += h0v * w0;
                acc[g][0][1] += h0v * w1;
                acc[g][1][0] += h1v * w0;
                acc[g][1][1] += h1v * w1;
            }
        }
        __syncthreads();
    }
    #pragma unroll
    for (int cb = 0; cb < 2; cb++) {
        int b = b0 + ty + 8 * cb;
        #pragma unroll
        for (int cj = 0; cj < 2; cj++) {
            int j = j0 + tx + 16 * cj;
            float gr = gi[b * G + j]           + acc[0][cb][cj] + bh[j];
            float gz = gi[b * G + H + j]       + acc[1][cb][cj] + bh[H + j];
            float gn = gi[b * G + 2 * H + j];
            float hn = acc[2][cb][cj] + bh[2 * H + j];
            float r = sigmoidf_(gr);
            float u = sigmoidf_(gz);
            float n = tanhf(gn + r * hn);
            float hp = hprev[b * H + j];
            hnext[b * H + j] = (1.0f - u) * n + u * hp;
        }
    }
}

// ---------------- encoder output: zm, zs, z, planar flow; writes out + g_z
// grid 2048 blocks, 256 threads: 4 rows per block, 64 threads per row.
__global__ void k_flow_enc(const float* __restrict__ head,
                           const float* __restrict__ eps_enc,
                           const float* __restrict__ w_flow,
                           const float* __restrict__ b_flow,
                           const float* __restrict__ u_flow,
                           float* __restrict__ out,
                           float* __restrict__ z_all) {
    __shared__ float red[4][64];
    int rl = threadIdx.x >> 6;           // 0..3
    int j = threadIdx.x & 63;
    int row = blockIdx.x * 4 + rl;       // = t*B + b
    int t = row >> 7;
    int b = row & 127;

    float zm = sigmoidf_(head[row * 128 + j]);
    float zs = softplusf_(head[row * 128 + 64 + j]);
    float eps = eps_enc[b * (T * Z) + t * Z + j];
    float z = eps * zs + zm;

    #pragma unroll
    for (int k = 0; k < KF; k++) {
        red[rl][j] = z * w_flow[(t * KF + k) * Z + j];
        __syncthreads();
        #pragma unroll
        for (int s = 32; s > 0; s >>= 1) {
            if (j < s) red[rl][j] += red[rl][j + s];
            __syncthreads();
        }
        float sv = red[rl][0] + b_flow[t * KF + k];
        __syncthreads();
        z += u_flow[(t * KF + k) * Z + j] * tanhf(sv);
    }

    int o = (b * T + t) * Z + j;
    out[2 + o]         = z;   // z section
    out[2 + S + o]     = zm;  // z_mean
    out[2 + 2 * S + o] = zs;  // z_std
    z_all[row * Z + j] = z;
}

// ---------------- decoder output: xm, xs, xo ----------------
__global__ void k_dec_out(const float* __restrict__ head,
                          const float* __restrict__ eps_dec,
                          float* __restrict__ out) {
    int i = blockIdx.x * blockDim.x + threadIdx.x;
    if (i >= S) return;
    int row = i >> 6;        // t*B+b
    int j = i & 63;
    int t = row >> 7;
    int b = row & 127;
    float xm = sigmoidf_(head[row * 128 + j]);
    float xs = softplusf_(head[row * 128 + 64 + j]);
    float eps = eps_dec[b * (T * X) + t * X + j];
    float xo = eps * xs + xm;
    int o = (b * T + t) * X + j;
    out[2 + 3 * S + o] = xo;
    out[2 + 4 * S + o] = xm;
    out[2 + 5 * S + o] = xs;
}

// ---------------- deterministic two-pass reduction ----------------
__global__ void k_reduce_partial(const float* __restrict__ x,
                                 const float* __restrict__ out,
                                 double* __restrict__ part) {
    __shared__ double sn[256];
    __shared__ double sk[256];
    double accN = 0.0, accK = 0.0;
    for (int i = blockIdx.x * 256 + threadIdx.x; i < S; i += 256 * 256) {
        float zm = out[2 + S + i];
        float zs = out[2 + 2 * S + i];
        accK += 1.0 + (double)zs - (double)zm * zm - exp((double)zs);
        float xm = out[2 + 4 * S + i];
        float xs = out[2 + 5 * S + i];
        accK += 1.0 + (double)xs - (double)xm * xm - exp((double)xs);
        float xv = x[i];
        double d = ((double)xv - (double)xm) * exp(-0.5 * (double)xs);
        accN += (double)xs + d * d;
    }
    sn[threadIdx.x] = accN;
    sk[threadIdx.x] = accK;
    __syncthreads();
    for (int s = 128; s > 0; s >>= 1) {
        if (threadIdx.x < s) {
            sn[threadIdx.x] += sn[threadIdx.x + s];
            sk[threadIdx.x] += sk[threadIdx.x + s];
        }
        __syncthreads();
    }
    if (threadIdx.x == 0) {
        part[blockIdx.x * 2]     = sn[0];
        part[blockIdx.x * 2 + 1] = sk[0];
    }
}

__global__ void k_reduce_final(const double* __restrict__ part,
                               float* __restrict__ out) {
    __shared__ double sn[256];
    __shared__ double sk[256];
    sn[threadIdx.x] = part[threadIdx.x * 2];
    sk[threadIdx.x] = part[threadIdx.x * 2 + 1];
    __syncthreads();
    for (int s = 128; s > 0; s >>= 1) {
        if (threadIdx.x < s) {
            sn[threadIdx.x] += sn[threadIdx.x + s];
            sk[threadIdx.x] += sk[threadIdx.x + s];
        }
        __syncthreads();
    }
    if (threadIdx.x == 0) {
        out[0] = (float)(0.5 * sn[0]);
        out[1] = (float)(-0.5 * sk[0]);
    }
}

// ---------------- launch ----------------
extern "C" void kernel_launch(void* const* d_in, const int* in_sizes, int n_in,
                              void* d_out, int out_size) {
    const float* x        = (const float*)d_in[0];
    const float* eps_enc  = (const float*)d_in[1];
    const float* eps_dec  = (const float*)d_in[2];
    const float* Wi_enc   = (const float*)d_in[3];
    const float* Wh_enc   = (const float*)d_in[4];
    const float* bi_enc   = (const float*)d_in[5];
    const float* bh_enc   = (const float*)d_in[6];
    const float* Wphi_enc = (const float*)d_in[7];
    const float* bphi_enc = (const float*)d_in[8];
    const float* W_zmean  = (const float*)d_in[9];
    const float* b_zmean  = (const float*)d_in[10];
    const float* W_zstd   = (const float*)d_in[11];
    const float* b_zstd   = (const float*)d_in[12];
    const float* w_flow   = (const float*)d_in[13];
    const float* b_flow   = (const float*)d_in[14];
    const float* u_flow   = (const float*)d_in[15];
    const float* Wi_dec   = (const float*)d_in[16];
    const float* Wh_dec   = (const float*)d_in[17];
    const float* bi_dec   = (const float*)d_in[18];
    const float* bh_dec   = (const float*)d_in[19];
    const float* Wphi_dec = (const float*)d_in[20];
    const float* bphi_dec = (const float*)d_in[21];
    const float* W_xmean  = (const float*)d_in[22];
    const float* b_xmean  = (const float*)d_in[23];
    const float* W_xstd   = (const float*)d_in[24];
    const float* b_xstd   = (const float*)d_in[25];
    float* out = (float*)d_out;

    float *p_xT, *p_gi, *p_h, *p_phi, *p_head, *p_z;
    double* p_part;
    cudaGetSymbolAddress((void**)&p_xT,   g_xT);
    cudaGetSymbolAddress((void**)&p_gi,   g_gi);
    cudaGetSymbolAddress((void**)&p_h,    g_h);
    cudaGetSymbolAddress((void**)&p_phi,  g_phi);
    cudaGetSymbolAddress((void**)&p_head, g_head);
    cudaGetSymbolAddress((void**)&p_z,    g_z);
    cudaGetSymbolAddress((void**)&p_part, g_part);

    // 0) rearrange x, zero h0
    k_transpose_x<<<(B * T * X + 255) / 256, 256>>>(x, p_xT);
    k_zero<<<(B * H + 255) / 256, 256>>>(p_h, B * H);

    // 1) gi_enc = xT @ Wi_enc.T + bi_enc   [8192 x 1536], K=64
    {
        dim3 grid(BT / 64, G / 64);
        k_gemm<<<grid, 256>>>(p_xT, X, Wi_enc, X, bi_enc, p_gi, G, X, 0);
    }
    // 2) encoder GRU scan
    {
        dim3 grid(B / 16, H / 32);
        for (int t = 0; t < T; t++) {
            k_gru_step<<<grid, 128>>>(p_gi + (size_t)t * B * G,
                                      p_h + (size_t)t * B * H,
                                      Wh_enc, bh_enc,
                                      p_h + (size_t)(t + 1) * B * H);
        }
    }
    // 3) phi_enc = relu(h_all @ Wphi_enc[:, :H].T + b)   [8192 x 512], K=512
    {
        dim3 grid(BT / 64, D / 64);
        k_gemm<<<grid, 256>>>(p_h + B * H, H, Wphi_enc, H + Z, bphi_enc,
                              p_phi, D, H, 1);
    }
    // 4) z heads (pre-activation) into g_head cols [0:64)=mean, [64:128)=std
    {
        dim3 grid(BT / 64, 1);
        k_gemm<<<grid, 256>>>(p_phi, D, W_zmean, D, b_zmean, p_head, 128, D, 0);
        k_gemm<<<grid, 256>>>(p_phi, D, W_zstd,  D, b_zstd,  p_head + 64, 128, D, 0);
    }
    // 5) flow + z outputs
    k_flow_enc<<<BT / 4, 256>>>(p_head, eps_enc, w_flow, b_flow, u_flow, out, p_z);

    // 6) gi_dec = z_all @ Wi_dec.T + bi_dec
    {
        dim3 grid(BT / 64, G / 64);
        k_gemm<<<grid, 256>>>(p_z, Z, Wi_dec, Z, bi_dec, p_gi, G, Z, 0);
    }
    // 7) decoder GRU scan (h_all[0] still zero)
    {
        dim3 grid(B / 16, H / 32);
        for (int t = 0; t < T; t++) {
            k_gru_step<<<grid, 128>>>(p_gi + (size_t)t * B * G,
                                      p_h + (size_t)t * B * H,
                                      Wh_dec, bh_dec,
                                      p_h + (size_t)(t + 1) * B * H);
        }
    }
    // 8) phi_dec = relu(h_all @ Wphi_dec.T + b)
    {
        dim3 grid(BT / 64, D / 64);
        k_gemm<<<grid, 256>>>(p_h + B * H, H, Wphi_dec, H, bphi_dec,
                              p_phi, D, H, 1);
    }
    // 9) x heads
    {
        dim3 grid(BT / 64, 1);
        k_gemm<<<grid, 256>>>(p_phi, D, W_xmean, D, b_xmean, p_head, 128, D, 0);
        k_gemm<<<grid, 256>>>(p_phi, D, W_xstd,  D, b_xstd,  p_head + 64, 128, D, 0);
    }
    // 10) decoder outputs
    k_dec_out<<<(S + 255) / 256, 256>>>(p_head, eps_dec, out);

    // 11) deterministic reductions for nll / kld
    k_reduce_partial<<<256, 256>>>(x, out, p_part);
    k_reduce_final<<<1, 256>>>(p_part, out);
}

// round 2
// speedup vs baseline: 4.1691x; 4.1691x over previous
#include <cuda_runtime.h>
#include <math.h>

// Problem dims
#define B   128
#define T   64
#define Xd  64
#define H   512
#define D   512
#define Z   64
#define KF  2
#define G   1536          // 3*H
#define BT  8192          // B*T
#define S   524288        // B*T*64
#define NBLK 128
#define SCAN_THREADS 256
// dynamic smem for scan: ws[512*12] + red[8*12*128] + sbh[16]
#define SCAN_SMEM ((512*12 + 8*12*128 + 16) * 4)

// ---------------- scratch ----------------
__device__ float  g_xT[BT * Xd];           // x rearranged to [t*B+b][X]
__device__ float  g_gi[BT * G];            // gi for enc, reused for dec
__device__ float  g_h[(T + 1) * H * B];    // h TRANSPOSED: [t][k][b], slab 0 = zeros
__device__ float  g_phi[BT * D];
__device__ float  g_head[BT * 128];
__device__ float  g_z[BT * Z];
__device__ double g_part[512];
__device__ unsigned g_bar_count = 0;
__device__ unsigned g_bar_gen = 0;

// ---------------- helpers ----------------
__device__ __forceinline__ float sigmoidf_(float v) { return 1.0f / (1.0f + expf(-v)); }
__device__ __forceinline__ float softplusf_(float v) { return (v > 20.0f) ? v : log1pf(expf(v)); }

__device__ __forceinline__ void fma2(unsigned long long &a, unsigned long long x, unsigned long long y) {
    asm("fma.rn.f32x2 %0, %1, %2, %0;" : "+l"(a) : "l"(x), "l"(y));
}
__device__ __forceinline__ unsigned long long pack2(float lo, float hi) {
    unsigned long long r;
    asm("mov.b64 %0, {%1, %2};" : "=l"(r) : "f"(lo), "f"(hi));
    return r;
}
__device__ __forceinline__ float2 unpack2(unsigned long long v) {
    float2 r;
    asm("mov.b64 {%0, %1}, %2;" : "=f"(r.x), "=f"(r.y) : "l"(v));
    return r;
}

// monotonic-counter grid barrier (no reset race); NBLK is a power of two
__device__ __forceinline__ void grid_barrier() {
    __threadfence();
    __syncthreads();
    if (threadIdx.x == 0) {
        volatile unsigned* vgen = &g_bar_gen;
        unsigned gen = *vgen;
        unsigned prev = atomicAdd(&g_bar_count, 1u);
        if ((prev & (NBLK - 1)) == (NBLK - 1)) {
            __threadfence();
            *vgen = gen + 1;
        } else {
            while (*vgen == gen) { }
            __threadfence();
        }
    }
    __syncthreads();
}

// ---------------- misc small kernels ----------------
__global__ void k_transpose_x(const float* __restrict__ x, float* __restrict__ xT) {
    int i = blockIdx.x * blockDim.x + threadIdx.x;
    if (i < B * T * Xd) {
        int b = i >> 12;
        int r = i & 4095;
        int t = r >> 6;
        int xi = r & 63;
        xT[((t << 7) + b) * Xd + xi] = x[i];
    }
}

__global__ void k_zero(float* __restrict__ p, int n) {
    int i = blockIdx.x * blockDim.x + threadIdx.x;
    if (i < n) p[i] = 0.0f;
}

// ---------------- generic tiled GEMM: C[m][n] = act(A[m][:] . W[n][:] + bias[n])
__global__ void k_gemm(const float* __restrict__ A, int lda,
                       const float* __restrict__ W, int ldw,
                       const float* __restrict__ bias,
                       float* __restrict__ C, int ldc,
                       int K, int act) {
    __shared__ float As[32][65];
    __shared__ float Ws[32][65];
    const int m0 = blockIdx.x * 64;
    const int n0 = blockIdx.y * 64;
    const int tx = threadIdx.x & 15;
    const int ty = threadIdx.x >> 4;
    float acc[4][4] = {{0.f}};

    for (int k0 = 0; k0 < K; k0 += 32) {
        #pragma unroll
        for (int i = threadIdx.x; i < 64 * 32; i += 256) {
            int k = i & 31, m = i >> 5;
            As[k][m] = A[(size_t)(m0 + m) * lda + k0 + k];
        }
        #pragma unroll
        for (int i = threadIdx.x; i < 64 * 32; i += 256) {
            int k = i & 31, n = i >> 5;
            Ws[k][n] = W[(size_t)(n0 + n) * ldw + k0 + k];
        }
        __syncthreads();
        #pragma unroll
        for (int k = 0; k < 32; k++) {
            float a[4], bv[4];
            #pragma unroll
            for (int i = 0; i < 4; i++) a[i] = As[k][ty + 16 * i];
            #pragma unroll
            for (int j = 0; j < 4; j++) bv[j] = Ws[k][tx + 16 * j];
            #pragma unroll
            for (int i = 0; i < 4; i++)
                #pragma unroll
                for (int j = 0; j < 4; j++)
                    acc[i][j] += a[i] * bv[j];
        }
        __syncthreads();
    }
    #pragma unroll
    for (int i = 0; i < 4; i++) {
        int m = m0 + ty + 16 * i;
        #pragma unroll
        for (int j = 0; j < 4; j++) {
            int n = n0 + tx + 16 * j;
            float v = acc[i][j] + bias[n];
            if (act == 1) v = fmaxf(v, 0.0f);
            C[(size_t)m * ldc + n] = v;
        }
    }
}

// ---------------- GEMM variant: A comes from transposed h [(t+1)][k][b]
// row m = t*B + b  ->  A[m][k] = hT[(t+1)*H*B + k*B + b]
__global__ void k_gemm_ht(const float* __restrict__ hT,
                          const float* __restrict__ W, int ldw,
                          const float* __restrict__ bias,
                          float* __restrict__ C, int ldc,
                          int K, int act) {
    __shared__ float As[32][65];
    __shared__ float Ws[32][65];
    const int m0 = blockIdx.x * 64;
    const int n0 = blockIdx.y * 64;
    const size_t slab = (size_t)((m0 >> 7) + 1) * (H * B);
    const int b0 = m0 & 127;
    const int tx = threadIdx.x & 15;
    const int ty = threadIdx.x >> 4;
    float acc[4][4] = {{0.f}};

    for (int k0 = 0; k0 < K; k0 += 32) {
        #pragma unroll
        for (int i = threadIdx.x; i < 64 * 32; i += 256) {
            int m = i & 63, k = i >> 6;
            As[k][m] = hT[slab + (size_t)(k0 + k) * B + b0 + m];
        }
        #pragma unroll
        for (int i = threadIdx.x; i < 64 * 32; i += 256) {
            int k = i & 31, n = i >> 5;
            Ws[k][n] = W[(size_t)(n0 + n) * ldw + k0 + k];
        }
        __syncthreads();
        #pragma unroll
        for (int k = 0; k < 32; k++) {
            float a[4], bv[4];
            #pragma unroll
            for (int i = 0; i < 4; i++) a[i] = As[k][ty + 16 * i];
            #pragma unroll
            for (int j = 0; j < 4; j++) bv[j] = Ws[k][tx + 16 * j];
            #pragma unroll
            for (int i = 0; i < 4; i++)
                #pragma unroll
                for (int j = 0; j < 4; j++)
                    acc[i][j] += a[i] * bv[j];
        }
        __syncthreads();
    }
    #pragma unroll
    for (int i = 0; i < 4; i++) {
        int m = m0 + ty + 16 * i;
        #pragma unroll
        for (int j = 0; j < 4; j++) {
            int n = n0 + tx + 16 * j;
            float v = acc[i][j] + bias[n];
            if (act == 1) v = fmaxf(v, 0.0f);
            C[(size_t)m * ldc + n] = v;
        }
    }
}

// ---------------- persistent GRU scan ----------------
// 128 blocks x 256 threads. Block owns hidden cols j0..j0+3 (x3 gates = 12 cols).
// Weights cached in smem for all 64 steps. h layout [t][k][b] (transposed).
extern __shared__ float smem_dyn[];

__global__ void __launch_bounds__(SCAN_THREADS, 1)
k_gru_scan(const float* __restrict__ gi,   // [T*B, G]
           const float* __restrict__ Wh,   // [G, H]
           const float* __restrict__ bh,   // [G]
           float* __restrict__ hT)         // [(T+1), H, B]
{
    float* ws  = smem_dyn;              // [512][12] : ws[k*12 + c]
    float* red = ws + 512 * 12;         // [8][12][128]
    float* sbh = red + 8 * 12 * 128;    // [12]
    const int tid  = threadIdx.x;
    const int warp = tid >> 5;
    const int lane = tid & 31;
    const int j0   = blockIdx.x * 4;

    // load weight slice (once): c = g*4 + jj
    for (int i = tid; i < 12 * 512; i += SCAN_THREADS) {
        int c = i >> 9, k = i & 511;
        ws[k * 12 + c] = Wh[((size_t)((c >> 2) * H + j0 + (c & 3))) * H + k];
    }
    if (tid < 12) sbh[tid] = bh[(tid >> 2) * H + j0 + (tid & 3)];
    __syncthreads();

    const int k0 = warp * 64;
    const int bbase = lane * 4;

    for (int t = 0; t < T; t++) {
        const float* hprev = hT + (size_t)t * (H * B);

        unsigned long long acc[4][6];
        #pragma unroll
        for (int i = 0; i < 4; i++)
            #pragma unroll
            for (int cp = 0; cp < 6; cp++) acc[i][cp] = 0ull;

        #pragma unroll 4
        for (int kk = 0; kk < 64; kk++) {
            int k = k0 + kk;
            float4 hv = *reinterpret_cast<const float4*>(hprev + (size_t)k * B + bbase);
            unsigned long long h2[4];
            h2[0] = pack2(hv.x, hv.x);
            h2[1] = pack2(hv.y, hv.y);
            h2[2] = pack2(hv.z, hv.z);
            h2[3] = pack2(hv.w, hv.w);
            const float* wrow = ws + k * 12;
            #pragma unroll
            for (int cp = 0; cp < 6; cp++) {
                unsigned long long w2 = *reinterpret_cast<const unsigned long long*>(wrow + cp * 2);
                #pragma unroll
                for (int i = 0; i < 4; i++) fma2(acc[i][cp], h2[i], w2);
            }
        }

        // write partials red[warp][c][b] with STS.128 over the 4 b per lane
        #pragma unroll
        for (int cp = 0; cp < 6; cp++) {
            float2 v0 = unpack2(acc[0][cp]);
            float2 v1 = unpack2(acc[1][cp]);
            float2 v2 = unpack2(acc[2][cp]);
            float2 v3 = unpack2(acc[3][cp]);
            float4 a  = make_float4(v0.x, v1.x, v2.x, v3.x);
            float4 b4 = make_float4(v0.y, v1.y, v2.y, v3.y);
            *reinterpret_cast<float4*>(red + ((size_t)(warp * 12 + 2 * cp)) * B + bbase)     = a;
            *reinterpret_cast<float4*>(red + ((size_t)(warp * 12 + 2 * cp + 1)) * B + bbase) = b4;
        }
        __syncthreads();

        // gate phase: 512 outputs (4 j x 128 b), 2 per thread
        #pragma unroll
        for (int oo = 0; oo < 2; oo++) {
            int o = tid + oo * 256;
            int jj = o >> 7;
            int b  = o & 127;
            float gr = 0.f, gz = 0.f, gn = 0.f;
            #pragma unroll
            for (int w = 0; w < 8; w++) {
                gr += red[(w * 12 + 0 + jj) * B + b];
                gz += red[(w * 12 + 4 + jj) * B + b];
                gn += red[(w * 12 + 8 + jj) * B + b];
            }
            size_t gbase = ((size_t)t * B + b) * G + (j0 + jj);
            float ir  = gi[gbase];
            float iz  = gi[gbase + H];
            float inn = gi[gbase + 2 * H];
            float r = sigmoidf_(ir + gr + sbh[jj]);
            float u = sigmoidf_(iz + gz + sbh[4 + jj]);
            float n = tanhf(inn + r * (gn + sbh[8 + jj]));
            float hp = hprev[(size_t)(j0 + jj) * B + b];
            hT[((size_t)(t + 1) * H + j0 + jj) * B + b] = (1.0f - u) * n + u * hp;
        }

        grid_barrier();
    }
}

// ---------------- encoder output: zm, zs, z, planar flow ----------------
__global__ void k_flow_enc(const float* __restrict__ head,
                           const float* __restrict__ eps_enc,
                           const float* __restrict__ w_flow,
                           const float* __restrict__ b_flow,
                           const float* __restrict__ u_flow,
                           float* __restrict__ out,
                           float* __restrict__ z_all) {
    __shared__ float red[4][64];
    int rl = threadIdx.x >> 6;
    int j = threadIdx.x & 63;
    int row = blockIdx.x * 4 + rl;       // t*B + b
    int t = row >> 7;
    int b = row & 127;

    float zm = sigmoidf_(head[row * 128 + j]);
    float zs = softplusf_(head[row * 128 + 64 + j]);
    float eps = eps_enc[b * (T * Z) + t * Z + j];
    float z = eps * zs + zm;

    #pragma unroll
    for (int k = 0; k < KF; k++) {
        red[rl][j] = z * w_flow[(t * KF + k) * Z + j];
        __syncthreads();
        #pragma unroll
        for (int s = 32; s > 0; s >>= 1) {
            if (j < s) red[rl][j] += red[rl][j + s];
            __syncthreads();
        }
        float sv = red[rl][0] + b_flow[t * KF + k];
        __syncthreads();
        z += u_flow[(t * KF + k) * Z + j] * tanhf(sv);
    }

    int o = (b * T + t) * Z + j;
    out[2 + o]         = z;
    out[2 + S + o]     = zm;
    out[2 + 2 * S + o] = zs;
    z_all[row * Z + j] = z;
}

// ---------------- decoder output ----------------
__global__ void k_dec_out(const float* __restrict__ head,
                          const float* __restrict__ eps_dec,
                          float* __restrict__ out) {
    int i = blockIdx.x * blockDim.x + threadIdx.x;
    if (i >= S) return;
    int row = i >> 6;
    int j = i & 63;
    int t = row >> 7;
    int b = row & 127;
    float xm = sigmoidf_(head[row * 128 + j]);
    float xs = softplusf_(head[row * 128 + 64 + j]);
    float eps = eps_dec[b * (T * Xd) + t * Xd + j];
    float xo = eps * xs + xm;
    int o = (b * T + t) * Xd + j;
    out[2 + 3 * S + o] = xo;
    out[2 + 4 * S + o] = xm;
    out[2 + 5 * S + o] = xs;
}

// ---------------- deterministic two-pass reduction ----------------
__global__ void k_reduce_partial(const float* __restrict__ x,
                                 const float* __restrict__ out,
                                 double* __restrict__ part) {
    __shared__ double sn[256];
    __shared__ double sk[256];
    double accN = 0.0, accK = 0.0;
    for (int i = blockIdx.x * 256 + threadIdx.x; i < S; i += 256 * 256) {
        float zm = out[2 + S + i];
        float zs = out[2 + 2 * S + i];
        accK += 1.0 + (double)zs - (double)zm * zm - exp((double)zs);
        float xm = out[2 + 4 * S + i];
        float xs = out[2 + 5 * S + i];
        accK += 1.0 + (double)xs - (double)xm * xm - exp((double)xs);
        float xv = x[i];
        double d = ((double)xv - (double)xm) * exp(-0.5 * (double)xs);
        accN += (double)xs + d * d;
    }
    sn[threadIdx.x] = accN;
    sk[threadIdx.x] = accK;
    __syncthreads();
    for (int s = 128; s > 0; s >>= 1) {
        if (threadIdx.x < s) {
            sn[threadIdx.x] += sn[threadIdx.x + s];
            sk[threadIdx.x] += sk[threadIdx.x + s];
        }
        __syncthreads();
    }
    if (threadIdx.x == 0) {
        part[blockIdx.x * 2]     = sn[0];
        part[blockIdx.x * 2 + 1] = sk[0];
    }
}

__global__ void k_reduce_final(const double* __restrict__ part,
                               float* __restrict__ out) {
    __shared__ double sn[256];
    __shared__ double sk[256];
    sn[threadIdx.x] = part[threadIdx.x * 2];
    sk[threadIdx.x] = part[threadIdx.x * 2 + 1];
    __syncthreads();
    for (int s = 128; s > 0; s >>= 1) {
        if (threadIdx.x < s) {
            sn[threadIdx.x] += sn[threadIdx.x + s];
            sk[threadIdx.x] += sk[threadIdx.x + s];
        }
        __syncthreads();
    }
    if (threadIdx.x == 0) {
        out[0] = (float)(0.5 * sn[0]);
        out[1] = (float)(-0.5 * sk[0]);
    }
}

// ---------------- launch ----------------
extern "C" void kernel_launch(void* const* d_in, const int* in_sizes, int n_in,
                              void* d_out, int out_size) {
    const float* x        = (const float*)d_in[0];
    const float* eps_enc  = (const float*)d_in[1];
    const float* eps_dec  = (const float*)d_in[2];
    const float* Wi_enc   = (const float*)d_in[3];
    const float* Wh_enc   = (const float*)d_in[4];
    const float* bi_enc   = (const float*)d_in[5];
    const float* bh_enc   = (const float*)d_in[6];
    const float* Wphi_enc = (const float*)d_in[7];
    const float* bphi_enc = (const float*)d_in[8];
    const float* W_zmean  = (const float*)d_in[9];
    const float* b_zmean  = (const float*)d_in[10];
    const float* W_zstd   = (const float*)d_in[11];
    const float* b_zstd   = (const float*)d_in[12];
    const float* w_flow   = (const float*)d_in[13];
    const float* b_flow   = (const float*)d_in[14];
    const float* u_flow   = (const float*)d_in[15];
    const float* Wi_dec   = (const float*)d_in[16];
    const float* Wh_dec   = (const float*)d_in[17];
    const float* bi_dec   = (const float*)d_in[18];
    const float* bh_dec   = (const float*)d_in[19];
    const float* Wphi_dec = (const float*)d_in[20];
    const float* bphi_dec = (const float*)d_in[21];
    const float* W_xmean  = (const float*)d_in[22];
    const float* b_xmean  = (const float*)d_in[23];
    const float* W_xstd   = (const float*)d_in[24];
    const float* b_xstd   = (const float*)d_in[25];
    float* out = (float*)d_out;

    float *p_xT, *p_gi, *p_h, *p_phi, *p_head, *p_z;
    double* p_part;
    cudaGetSymbolAddress((void**)&p_xT,   g_xT);
    cudaGetSymbolAddress((void**)&p_gi,   g_gi);
    cudaGetSymbolAddress((void**)&p_h,    g_h);
    cudaGetSymbolAddress((void**)&p_phi,  g_phi);
    cudaGetSymbolAddress((void**)&p_head, g_head);
    cudaGetSymbolAddress((void**)&p_z,    g_z);
    cudaGetSymbolAddress((void**)&p_part, g_part);

    cudaFuncSetAttribute(k_gru_scan, cudaFuncAttributeMaxDynamicSharedMemorySize, SCAN_SMEM);

    // 0) rearrange x, zero h slab 0
    k_transpose_x<<<(B * T * Xd + 255) / 256, 256>>>(x, p_xT);
    k_zero<<<(H * B + 255) / 256, 256>>>(p_h, H * B);

    // 1) gi_enc = xT @ Wi_enc.T + bi_enc   [8192 x 1536], K=64
    {
        dim3 grid(BT / 64, G / 64);
        k_gemm<<<grid, 256>>>(p_xT, Xd, Wi_enc, Xd, bi_enc, p_gi, G, Xd, 0);
    }
    // 2) encoder GRU scan (persistent)
    k_gru_scan<<<NBLK, SCAN_THREADS, SCAN_SMEM>>>(p_gi, Wh_enc, bh_enc, p_h);

    // 3) phi_enc = relu(h_all @ Wphi_enc[:, :H].T + b)
    {
        dim3 grid(BT / 64, D / 64);
        k_gemm_ht<<<grid, 256>>>(p_h, Wphi_enc, H + Z, bphi_enc, p_phi, D, H, 1);
    }
    // 4) z heads
    {
        dim3 grid(BT / 64, 1);
        k_gemm<<<grid, 256>>>(p_phi, D, W_zmean, D, b_zmean, p_head, 128, D, 0);
        k_gemm<<<grid, 256>>>(p_phi, D, W_zstd,  D, b_zstd,  p_head + 64, 128, D, 0);
    }
    // 5) flow + z outputs
    k_flow_enc<<<BT / 4, 256>>>(p_head, eps_enc, w_flow, b_flow, u_flow, out, p_z);

    // 6) gi_dec = z_all @ Wi_dec.T + bi_dec
    {
        dim3 grid(BT / 64, G / 64);
        k_gemm<<<grid, 256>>>(p_z, Z, Wi_dec, Z, bi_dec, p_gi, G, Z, 0);
    }
    // 7) decoder GRU scan (h slab 0 still zero)
    k_gru_scan<<<NBLK, SCAN_THREADS, SCAN_SMEM>>>(p_gi, Wh_dec, bh_dec, p_h);

    // 8) phi_dec
    {
        dim3 grid(BT / 64, D / 64);
        k_gemm_ht<<<grid, 256>>>(p_h, Wphi_dec, H, bphi_dec, p_phi, D, H, 1);
    }
    // 9) x heads
    {
        dim3 grid(BT / 64, 1);
        k_gemm<<<grid, 256>>>(p_phi, D, W_xmean, D, b_xmean, p_head, 128, D, 0);
        k_gemm<<<grid, 256>>>(p_phi, D, W_xstd,  D, b_xstd,  p_head + 64, 128, D, 0);
    }
    // 10) decoder outputs
    k_dec_out<<<(S + 255) / 256, 256>>>(p_head, eps_dec, out);

    // 11) reductions
    k_reduce_partial<<<256, 256>>>(x, out, p_part);
    k_reduce_final<<<1, 256>>>(p_part, out);
}

// round 3
// speedup vs baseline: 5.4240x; 1.3010x over previous
#include <cuda_runtime.h>
#include <math.h>

// Problem dims
#define B   128
#define T   64
#define Xd  64
#define H   512
#define D   512
#define Z   64
#define KF  2
#define G   1536          // 3*H
#define BT  8192          // B*T
#define S   524288        // B*T*64
#define NBLK 128
#define SCAN_THREADS 512
#define SCAN_WARPS 16
// dynamic smem for scan: ws[512*12] + red[16*12*128] + sbh[16]
#define SCAN_SMEM ((512*12 + SCAN_WARPS*12*128 + 16) * 4)

// ---------------- scratch ----------------
__device__ float  g_xT[BT * Xd];           // x rearranged to [t*B+b][X]
__device__ float  g_gi[T * G * B];         // gi TRANSPOSED: [t][col][b]
__device__ float  g_h[(T + 1) * H * B];    // h TRANSPOSED: [t][k][b], slab 0 = zeros
__device__ float  g_phi[BT * D];
__device__ float  g_head[BT * 128];
__device__ float  g_z[BT * Z];
__device__ double g_part[512];
__device__ unsigned g_bar_count = 0;
__device__ unsigned g_bar_gen = 0;

// ---------------- helpers ----------------
__device__ __forceinline__ float sigmoidf_(float v) { return 1.0f / (1.0f + expf(-v)); }
__device__ __forceinline__ float softplusf_(float v) { return (v > 20.0f) ? v : log1pf(expf(v)); }

__device__ __forceinline__ void fma2(unsigned long long &a, unsigned long long x, unsigned long long y) {
    asm("fma.rn.f32x2 %0, %1, %2, %0;" : "+l"(a) : "l"(x), "l"(y));
}
__device__ __forceinline__ unsigned long long pack2(float lo, float hi) {
    unsigned long long r;
    asm("mov.b64 %0, {%1, %2};" : "=l"(r) : "f"(lo), "f"(hi));
    return r;
}
__device__ __forceinline__ float2 unpack2(unsigned long long v) {
    float2 r;
    asm("mov.b64 {%0, %1}, %2;" : "=f"(r.x), "=f"(r.y) : "l"(v));
    return r;
}

// monotonic-counter grid barrier (no reset race); NBLK is a power of two
__device__ __forceinline__ void grid_barrier() {
    __threadfence();
    __syncthreads();
    if (threadIdx.x == 0) {
        volatile unsigned* vgen = &g_bar_gen;
        unsigned gen = *vgen;
        unsigned prev = atomicAdd(&g_bar_count, 1u);
        if ((prev & (NBLK - 1)) == (NBLK - 1)) {
            __threadfence();
            *vgen = gen + 1;
        } else {
            while (*vgen == gen) { }
            __threadfence();
        }
    }
    __syncthreads();
}

// ---------------- misc small kernels ----------------
__global__ void k_transpose_x(const float* __restrict__ x, float* __restrict__ xT) {
    int i = blockIdx.x * blockDim.x + threadIdx.x;
    if (i < B * T * Xd) {
        int b = i >> 12;
        int r = i & 4095;
        int t = r >> 6;
        int xi = r & 63;
        xT[((t << 7) + b) * Xd + xi] = x[i];
    }
}

__global__ void k_zero(float* __restrict__ p, int n) {
    int i = blockIdx.x * blockDim.x + threadIdx.x;
    if (i < n) p[i] = 0.0f;
}

// ---------------- generic tiled GEMM with f32x2 accumulate
// C[m][n] = act(A[m][:] . W[n][:] + bias[n])
// cmode 0: row-major C[m*ldc+n]
// cmode 1: scan layout C[((m/B... t)*ldc + n)*B + (m%B)]  (t = m0>>7)
__global__ void __launch_bounds__(256)
k_gemm(const float* __restrict__ A, int lda,
       const float* __restrict__ W, int ldw,
       const float* __restrict__ bias,
       float* __restrict__ C, int ldc,
       int K, int act, int cmode) {
    __shared__ float sm[4160];           // As[32][65] | Ws[32][65]; reused as stage[64][65]
    float* As = sm;
    float* Ws = sm + 2080;
    const int m0 = blockIdx.x * 64;
    const int n0 = blockIdx.y * 64;
    const int tx = threadIdx.x & 15;
    const int ty = threadIdx.x >> 4;
    unsigned long long acc2[4][2];
    #pragma unroll
    for (int i = 0; i < 4; i++) { acc2[i][0] = 0ull; acc2[i][1] = 0ull; }

    for (int k0 = 0; k0 < K; k0 += 32) {
        #pragma unroll
        for (int i = threadIdx.x; i < 64 * 32; i += 256) {
            int k = i & 31, m = i >> 5;
            As[k * 65 + m] = A[(size_t)(m0 + m) * lda + k0 + k];
        }
        #pragma unroll
        for (int i = threadIdx.x; i < 64 * 32; i += 256) {
            int k = i & 31, n = i >> 5;
            Ws[k * 65 + n] = W[(size_t)(n0 + n) * ldw + k0 + k];
        }
        __syncthreads();
        #pragma unroll
        for (int k = 0; k < 32; k++) {
            float a[4], bv[4];
            #pragma unroll
            for (int i = 0; i < 4; i++) a[i] = As[k * 65 + ty + 16 * i];
            #pragma unroll
            for (int j = 0; j < 4; j++) bv[j] = Ws[k * 65 + tx + 16 * j];
            unsigned long long y0 = pack2(bv[0], bv[1]);
            unsigned long long y1 = pack2(bv[2], bv[3]);
            #pragma unroll
            for (int i = 0; i < 4; i++) {
                unsigned long long xa = pack2(a[i], a[i]);
                fma2(acc2[i][0], xa, y0);
                fma2(acc2[i][1], xa, y1);
            }
        }
        __syncthreads();
    }

    float c[4][4];
    #pragma unroll
    for (int i = 0; i < 4; i++) {
        float2 p0 = unpack2(acc2[i][0]);
        float2 p1 = unpack2(acc2[i][1]);
        c[i][0] = p0.x; c[i][1] = p0.y; c[i][2] = p1.x; c[i][3] = p1.y;
    }

    if (cmode == 0) {
        #pragma unroll
        for (int i = 0; i < 4; i++) {
            int m = m0 + ty + 16 * i;
            #pragma unroll
            for (int j = 0; j < 4; j++) {
                int n = n0 + tx + 16 * j;
                float v = c[i][j] + bias[n];
                if (act == 1) v = fmaxf(v, 0.0f);
                C[(size_t)m * ldc + n] = v;
            }
        }
    } else {
        // stage to smem then coalesced transposed write: C[(t*ldc + n)*B + b]
        float* stage = sm;   // [64][65], n-major
        #pragma unroll
        for (int i = 0; i < 4; i++) {
            #pragma unroll
            for (int j = 0; j < 4; j++) {
                stage[(tx + 16 * j) * 65 + ty + 16 * i] = c[i][j] + bias[n0 + tx + 16 * j];
            }
        }
        __syncthreads();
        const int t = m0 >> 7;
        const int b0 = m0 & 127;
        #pragma unroll
        for (int i = threadIdx.x; i < 4096; i += 256) {
            int n = i >> 6, mb = i & 63;
            C[((size_t)t * ldc + n0 + n) * B + b0 + mb] = stage[n * 65 + mb];
        }
    }
}

// ---------------- GEMM variant: A from transposed h [(t+1)][k][b] ----------------
__global__ void __launch_bounds__(256)
k_gemm_ht(const float* __restrict__ hT,
          const float* __restrict__ W, int ldw,
          const float* __restrict__ bias,
          float* __restrict__ C, int ldc,
          int K, int act) {
    __shared__ float sm[4160];
    float* As = sm;
    float* Ws = sm + 2080;
    const int m0 = blockIdx.x * 64;
    const int n0 = blockIdx.y * 64;
    const size_t slab = (size_t)((m0 >> 7) + 1) * (H * B);
    const int b0 = m0 & 127;
    const int tx = threadIdx.x & 15;
    const int ty = threadIdx.x >> 4;
    unsigned long long acc2[4][2];
    #pragma unroll
    for (int i = 0; i < 4; i++) { acc2[i][0] = 0ull; acc2[i][1] = 0ull; }

    for (int k0 = 0; k0 < K; k0 += 32) {
        #pragma unroll
        for (int i = threadIdx.x; i < 64 * 32; i += 256) {
            int m = i & 63, k = i >> 6;
            As[k * 65 + m] = hT[slab + (size_t)(k0 + k) * B + b0 + m];
        }
        #pragma unroll
        for (int i = threadIdx.x; i < 64 * 32; i += 256) {
            int k = i & 31, n = i >> 5;
            Ws[k * 65 + n] = W[(size_t)(n0 + n) * ldw + k0 + k];
        }
        __syncthreads();
        #pragma unroll
        for (int k = 0; k < 32; k++) {
            float a[4], bv[4];
            #pragma unroll
            for (int i = 0; i < 4; i++) a[i] = As[k * 65 + ty + 16 * i];
            #pragma unroll
            for (int j = 0; j < 4; j++) bv[j] = Ws[k * 65 + tx + 16 * j];
            unsigned long long y0 = pack2(bv[0], bv[1]);
            unsigned long long y1 = pack2(bv[2], bv[3]);
            #pragma unroll
            for (int i = 0; i < 4; i++) {
                unsigned long long xa = pack2(a[i], a[i]);
                fma2(acc2[i][0], xa, y0);
                fma2(acc2[i][1], xa, y1);
            }
        }
        __syncthreads();
    }
    #pragma unroll
    for (int i = 0; i < 4; i++) {
        float2 p0 = unpack2(acc2[i][0]);
        float2 p1 = unpack2(acc2[i][1]);
        float cv[4] = {p0.x, p0.y, p1.x, p1.y};
        int m = m0 + ty + 16 * i;
        #pragma unroll
        for (int j = 0; j < 4; j++) {
            int n = n0 + tx + 16 * j;
            float v = cv[j] + bias[n];
            if (act == 1) v = fmaxf(v, 0.0f);
            C[(size_t)m * ldc + n] = v;
        }
    }
}

// ---------------- persistent GRU scan ----------------
// 128 blocks x 512 threads. Block owns hidden cols j0..j0+3 (x3 gates = 12 cols).
// Warp w owns k-slice [w*32, w*32+32). gi in [t][col][b] layout (coalesced).
extern __shared__ float smem_dyn[];

__global__ void __launch_bounds__(SCAN_THREADS, 1)
k_gru_scan(const float* __restrict__ giT,  // [T][G][B]
           const float* __restrict__ Wh,   // [G, H]
           const float* __restrict__ bh,   // [G]
           float* __restrict__ hT)         // [(T+1), H, B]
{
    float* ws  = smem_dyn;                     // [512][12] : ws[k*12 + c], c = g*4+jj
    float* red = ws + 512 * 12;                // [16][12][128]
    float* sbh = red + SCAN_WARPS * 12 * 128;  // [12]
    const int tid  = threadIdx.x;
    const int warp = tid >> 5;
    const int lane = tid & 31;
    const int j0   = blockIdx.x * 4;

    for (int i = tid; i < 12 * 512; i += SCAN_THREADS) {
        int c = i >> 9, k = i & 511;
        ws[k * 12 + c] = Wh[((size_t)((c >> 2) * H + j0 + (c & 3))) * H + k];
    }
    if (tid < 12) sbh[tid] = bh[(tid >> 2) * H + j0 + (tid & 3)];
    __syncthreads();

    const int k0 = warp * 32;
    const int bbase = lane * 4;

    for (int t = 0; t < T; t++) {
        const float* hprev = hT + (size_t)t * (H * B);

        unsigned long long acc[4][6];
        #pragma unroll
        for (int i = 0; i < 4; i++)
            #pragma unroll
            for (int cp = 0; cp < 6; cp++) acc[i][cp] = 0ull;

        #pragma unroll 4
        for (int kk = 0; kk < 32; kk++) {
            int k = k0 + kk;
            float4 hv = *reinterpret_cast<const float4*>(hprev + (size_t)k * B + bbase);
            unsigned long long h2[4];
            h2[0] = pack2(hv.x, hv.x);
            h2[1] = pack2(hv.y, hv.y);
            h2[2] = pack2(hv.z, hv.z);
            h2[3] = pack2(hv.w, hv.w);
            const float* wrow = ws + k * 12;
            #pragma unroll
            for (int cp = 0; cp < 6; cp++) {
                unsigned long long w2 = *reinterpret_cast<const unsigned long long*>(wrow + cp * 2);
                #pragma unroll
                for (int i = 0; i < 4; i++) fma2(acc[i][cp], h2[i], w2);
            }
        }

        #pragma unroll
        for (int cp = 0; cp < 6; cp++) {
            float2 v0 = unpack2(acc[0][cp]);
            float2 v1 = unpack2(acc[1][cp]);
            float2 v2 = unpack2(acc[2][cp]);
            float2 v3 = unpack2(acc[3][cp]);
            float4 a  = make_float4(v0.x, v1.x, v2.x, v3.x);
            float4 b4 = make_float4(v0.y, v1.y, v2.y, v3.y);
            *reinterpret_cast<float4*>(red + ((size_t)(warp * 12 + 2 * cp)) * B + bbase)     = a;
            *reinterpret_cast<float4*>(red + ((size_t)(warp * 12 + 2 * cp + 1)) * B + bbase) = b4;
        }
        __syncthreads();

        // gate phase: 512 outputs (4 j x 128 b), one per thread; gi reads coalesced
        {
            int jj = tid >> 7;
            int b  = tid & 127;
            float gr = 0.f, gz = 0.f, gn = 0.f;
            #pragma unroll
            for (int w = 0; w < SCAN_WARPS; w++) {
                gr += red[(w * 12 + 0 + jj) * B + b];
                gz += red[(w * 12 + 4 + jj) * B + b];
                gn += red[(w * 12 + 8 + jj) * B + b];
            }
            size_t gibase = ((size_t)t * G + j0 + jj) * B + b;
            float ir  = giT[gibase];
            float iz  = giT[gibase + (size_t)H * B];
            float inn = giT[gibase + (size_t)2 * H * B];
            float r = sigmoidf_(ir + gr + sbh[jj]);
            float u = sigmoidf_(iz + gz + sbh[4 + jj]);
            float n = tanhf(inn + r * (gn + sbh[8 + jj]));
            float hp = hprev[(size_t)(j0 + jj) * B + b];
            hT[((size_t)(t + 1) * H + j0 + jj) * B + b] = (1.0f - u) * n + u * hp;
        }

        grid_barrier();
    }
}

// ---------------- encoder output: zm, zs, z, planar flow ----------------
__global__ void k_flow_enc(const float* __restrict__ head,
                           const float* __restrict__ eps_enc,
                           const float* __restrict__ w_flow,
                           const float* __restrict__ b_flow,
                           const float* __restrict__ u_flow,
                           float* __restrict__ out,
                           float* __restrict__ z_all) {
    __shared__ float red[4][64];
    int rl = threadIdx.x >> 6;
    int j = threadIdx.x & 63;
    int row = blockIdx.x * 4 + rl;       // t*B + b
    int t = row >> 7;
    int b = row & 127;

    float zm = sigmoidf_(head[row * 128 + j]);
    float zs = softplusf_(head[row * 128 + 64 + j]);
    float eps = eps_enc[b * (T * Z) + t * Z + j];
    float z = eps * zs + zm;

    #pragma unroll
    for (int k = 0; k < KF; k++) {
        red[rl][j] = z * w_flow[(t * KF + k) * Z + j];
        __syncthreads();
        #pragma unroll
        for (int s = 32; s > 0; s >>= 1) {
            if (j < s) red[rl][j] += red[rl][j + s];
            __syncthreads();
        }
        float sv = red[rl][0] + b_flow[t * KF + k];
        __syncthreads();
        z += u_flow[(t * KF + k) * Z + j] * tanhf(sv);
    }

    int o = (b * T + t) * Z + j;
    out[2 + o]         = z;
    out[2 + S + o]     = zm;
    out[2 + 2 * S + o] = zs;
    z_all[row * Z + j] = z;
}

// ---------------- decoder output ----------------
__global__ void k_dec_out(const float* __restrict__ head,
                          const float* __restrict__ eps_dec,
                          float* __restrict__ out) {
    int i = blockIdx.x * blockDim.x + threadIdx.x;
    if (i >= S) return;
    int row = i >> 6;
    int j = i & 63;
    int t = row >> 7;
    int b = row & 127;
    float xm = sigmoidf_(head[row * 128 + j]);
    float xs = softplusf_(head[row * 128 + 64 + j]);
    float eps = eps_dec[b * (T * Xd) + t * Xd + j];
    float xo = eps * xs + xm;
    int o = (b * T + t) * Xd + j;
    out[2 + 3 * S + o] = xo;
    out[2 + 4 * S + o] = xm;
    out[2 + 5 * S + o] = xs;
}

// ---------------- deterministic two-pass reduction ----------------
__global__ void k_reduce_partial(const float* __restrict__ x,
                                 const float* __restrict__ out,
                                 double* __restrict__ part) {
    __shared__ double sn[256];
    __shared__ double sk[256];
    double accN = 0.0, accK = 0.0;
    for (int i = blockIdx.x * 256 + threadIdx.x; i < S; i += 256 * 256) {
        float zm = out[2 + S + i];
        float zs = out[2 + 2 * S + i];
        accK += 1.0 + (double)zs - (double)zm * zm - exp((double)zs);
        float xm = out[2 + 4 * S + i];
        float xs = out[2 + 5 * S + i];
        accK += 1.0 + (double)xs - (double)xm * xm - exp((double)xs);
        float xv = x[i];
        double d = ((double)xv - (double)xm) * exp(-0.5 * (double)xs);
        accN += (double)xs + d * d;
    }
    sn[threadIdx.x] = accN;
    sk[threadIdx.x] = accK;
    __syncthreads();
    for (int s = 128; s > 0; s >>= 1) {
        if (threadIdx.x < s) {
            sn[threadIdx.x] += sn[threadIdx.x + s];
            sk[threadIdx.x] += sk[threadIdx.x + s];
        }
        __syncthreads();
    }
    if (threadIdx.x == 0) {
        part[blockIdx.x * 2]     = sn[0];
        part[blockIdx.x * 2 + 1] = sk[0];
    }
}

__global__ void k_reduce_final(const double* __restrict__ part,
                               float* __restrict__ out) {
    __shared__ double sn[256];
    __shared__ double sk[256];
    sn[threadIdx.x] = part[threadIdx.x * 2];
    sk[threadIdx.x] = part[threadIdx.x * 2 + 1];
    __syncthreads();
    for (int s = 128; s > 0; s >>= 1) {
        if (threadIdx.x < s) {
            sn[threadIdx.x] += sn[threadIdx.x + s];
            sk[threadIdx.x] += sk[threadIdx.x + s];
        }
        __syncthreads();
    }
    if (threadIdx.x == 0) {
        out[0] = (float)(0.5 * sn[0]);
        out[1] = (float)(-0.5 * sk[0]);
    }
}

// ---------------- launch ----------------
extern "C" void kernel_launch(void* const* d_in, const int* in_sizes, int n_in,
                              void* d_out, int out_size) {
    const float* x        = (const float*)d_in[0];
    const float* eps_enc  = (const float*)d_in[1];
    const float* eps_dec  = (const float*)d_in[2];
    const float* Wi_enc   = (const float*)d_in[3];
    const float* Wh_enc   = (const float*)d_in[4];
    const float* bi_enc   = (const float*)d_in[5];
    const float* bh_enc   = (const float*)d_in[6];
    const float* Wphi_enc = (const float*)d_in[7];
    const float* bphi_enc = (const float*)d_in[8];
    const float* W_zmean  = (const float*)d_in[9];
    const float* b_zmean  = (const float*)d_in[10];
    const float* W_zstd   = (const float*)d_in[11];
    const float* b_zstd   = (const float*)d_in[12];
    const float* w_flow   = (const float*)d_in[13];
    const float* b_flow   = (const float*)d_in[14];
    const float* u_flow   = (const float*)d_in[15];
    const float* Wi_dec   = (const float*)d_in[16];
    const float* Wh_dec   = (const float*)d_in[17];
    const float* bi_dec   = (const float*)d_in[18];
    const float* bh_dec   = (const float*)d_in[19];
    const float* Wphi_dec = (const float*)d_in[20];
    const float* bphi_dec = (const float*)d_in[21];
    const float* W_xmean  = (const float*)d_in[22];
    const float* b_xmean  = (const float*)d_in[23];
    const float* W_xstd   = (const float*)d_in[24];
    const float* b_xstd   = (const float*)d_in[25];
    float* out = (float*)d_out;

    float *p_xT, *p_gi, *p_h, *p_phi, *p_head, *p_z;
    double* p_part;
    cudaGetSymbolAddress((void**)&p_xT,   g_xT);
    cudaGetSymbolAddress((void**)&p_gi,   g_gi);
    cudaGetSymbolAddress((void**)&p_h,    g_h);
    cudaGetSymbolAddress((void**)&p_phi,  g_phi);
    cudaGetSymbolAddress((void**)&p_head, g_head);
    cudaGetSymbolAddress((void**)&p_z,    g_z);
    cudaGetSymbolAddress((void**)&p_part, g_part);

    cudaFuncSetAttribute(k_gru_scan, cudaFuncAttributeMaxDynamicSharedMemorySize, SCAN_SMEM);

    // 0) rearrange x, zero h slab 0
    k_transpose_x<<<(B * T * Xd + 255) / 256, 256>>>(x, p_xT);
    k_zero<<<(H * B + 255) / 256, 256>>>(p_h, H * B);

    // 1) gi_enc = xT @ Wi_enc.T + bi_enc -> transposed [t][col][b]
    {
        dim3 grid(BT / 64, G / 64);
        k_gemm<<<grid, 256>>>(p_xT, Xd, Wi_enc, Xd, bi_enc, p_gi, G, Xd, 0, 1);
    }
    // 2) encoder GRU scan (persistent)
    k_gru_scan<<<NBLK, SCAN_THREADS, SCAN_SMEM>>>(p_gi, Wh_enc, bh_enc, p_h);

    // 3) phi_enc = relu(h_all @ Wphi_enc[:, :H].T + b)
    {
        dim3 grid(BT / 64, D / 64);
        k_gemm_ht<<<grid, 256>>>(p_h, Wphi_enc, H + Z, bphi_enc, p_phi, D, H, 1);
    }
    // 4) z heads
    {
        dim3 grid(BT / 64, 1);
        k_gemm<<<grid, 256>>>(p_phi, D, W_zmean, D, b_zmean, p_head, 128, D, 0, 0);
        k_gemm<<<grid, 256>>>(p_phi, D, W_zstd,  D, b_zstd,  p_head + 64, 128, D, 0, 0);
    }
    // 5) flow + z outputs
    k_flow_enc<<<BT / 4, 256>>>(p_head, eps_enc, w_flow, b_flow, u_flow, out, p_z);

    // 6) gi_dec = z_all @ Wi_dec.T + bi_dec -> transposed
    {
        dim3 grid(BT / 64, G / 64);
        k_gemm<<<grid, 256>>>(p_z, Z, Wi_dec, Z, bi_dec, p_gi, G, Z, 0, 1);
    }
    // 7) decoder GRU scan (h slab 0 still zero)
    k_gru_scan<<<NBLK, SCAN_THREADS, SCAN_SMEM>>>(p_gi, Wh_dec, bh_dec, p_h);

    // 8) phi_dec
    {
        dim3 grid(BT / 64, D / 64);
        k_gemm_ht<<<grid, 256>>>(p_h, Wphi_dec, H, bphi_dec, p_phi, D, H, 1);
    }
    // 9) x heads
    {
        dim3 grid(BT / 64, 1);
        k_gemm<<<grid, 256>>>(p_phi, D, W_xmean, D, b_xmean, p_head, 128, D, 0, 0);
        k_gemm<<<grid, 256>>>(p_phi, D, W_xstd,  D, b_xstd,  p_head + 64, 128, D, 0, 0);
    }
    // 10) decoder outputs
    k_dec_out<<<(S + 255) / 256, 256>>>(p_head, eps_dec, out);

    // 11) reductions
    k_reduce_partial<<<256, 256>>>(x, out, p_part);
    k_reduce_final<<<1, 256>>>(p_part, out);
}

// round 4
// speedup vs baseline: 5.6145x; 1.0351x over previous
#include <cuda_runtime.h>
#include <math.h>

// Problem dims
#define B   128
#define T   64
#define Xd  64
#define H   512
#define D   512
#define Z   64
#define KF  2
#define G   1536          // 3*H
#define BT  8192          // B*T
#define S   524288        // B*T*64
#define NBLK 128
#define SCAN_THREADS 512
#define SCAN_WARPS 16
#define SCAN_SMEM ((512*12 + SCAN_WARPS*12*128 + 16) * 4)

typedef unsigned long long ull;

// ---------------- scratch ----------------
__device__ float  g_xT[BT * Xd];           // x rearranged to [t*B+b][X]
__device__ float  g_gi[T * G * B];         // gi TRANSPOSED: [t][col][b]
__device__ float  g_h[(T + 1) * H * B];    // h TRANSPOSED: [t][k][b], slab 0 = zeros
__device__ float  g_phi[BT * D];
__device__ float  g_head[BT * 128];
__device__ float  g_z[BT * Z];
__device__ float  g_Whead[128 * 512];
__device__ float  g_bhead[128];
__device__ double g_part[512];
__device__ unsigned g_bar_count = 0;
__device__ unsigned g_bar_gen = 0;

// ---------------- helpers ----------------
__device__ __forceinline__ float sigmoidf_(float v) { return 1.0f / (1.0f + expf(-v)); }
__device__ __forceinline__ float softplusf_(float v) { return (v > 20.0f) ? v : log1pf(expf(v)); }
// fast (MUFU-based) variants for the scan hot path
__device__ __forceinline__ float fsigmoid_(float v) { return 1.0f / (1.0f + __expf(-v)); }
__device__ __forceinline__ float ftanh_(float v) { return 1.0f - 2.0f / (__expf(2.0f * v) + 1.0f); }

__device__ __forceinline__ void fma2(ull &a, ull x, ull y) {
    asm("fma.rn.f32x2 %0, %1, %2, %0;" : "+l"(a) : "l"(x), "l"(y));
}
__device__ __forceinline__ ull pack2(float lo, float hi) {
    ull r;
    asm("mov.b64 %0, {%1, %2};" : "=l"(r) : "f"(lo), "f"(hi));
    return r;
}
__device__ __forceinline__ float2 unpack2(ull v) {
    float2 r;
    asm("mov.b64 {%0, %1}, %2;" : "=f"(r.x), "=f"(r.y) : "l"(v));
    return r;
}

// monotonic-counter grid barrier (no reset race); NBLK is a power of two
__device__ __forceinline__ void grid_barrier() {
    __threadfence();
    __syncthreads();
    if (threadIdx.x == 0) {
        volatile unsigned* vgen = &g_bar_gen;
        unsigned gen = *vgen;
        unsigned prev = atomicAdd(&g_bar_count, 1u);
        if ((prev & (NBLK - 1)) == (NBLK - 1)) {
            __threadfence();
            *vgen = gen + 1;
        } else {
            while (*vgen == gen) { }
            __threadfence();
        }
    }
    __syncthreads();
}

// ---------------- misc small kernels ----------------
__global__ void k_transpose_x(const float* __restrict__ x, float* __restrict__ xT) {
    int i = blockIdx.x * blockDim.x + threadIdx.x;
    if (i < B * T * Xd) {
        int b = i >> 12;
        int r = i & 4095;
        int t = r >> 6;
        int xi = r & 63;
        xT[((t << 7) + b) * Xd + xi] = x[i];
    }
}

__global__ void k_zero(float* __restrict__ p, int n) {
    int i = blockIdx.x * blockDim.x + threadIdx.x;
    if (i < n) p[i] = 0.0f;
}

// pack two [64, 512] head weight matrices + biases into one [128, 512]
__global__ void k_pack_head(const float* __restrict__ Wa, const float* __restrict__ ba,
                            const float* __restrict__ Wb, const float* __restrict__ bb,
                            float* __restrict__ Wh, float* __restrict__ bhp) {
    int i = blockIdx.x * blockDim.x + threadIdx.x;
    if (i < 64 * 512) {
        Wh[i] = Wa[i];
        Wh[64 * 512 + i] = Wb[i];
    }
    if (i < 64) {
        bhp[i] = ba[i];
        bhp[64 + i] = bb[i];
    }
}

// ---------------- tiled GEMM 128x128, 256 threads, 8x8 per thread ----------------
// C[m][n] = act(A[m][:] . W[n][:] + bias[n])
// cmode 0: row-major C[m*ldc+n]
// cmode 1: scan layout C[(t*ldc + n)*B + b], t = blockIdx.x, b = m&127 (m-tile == B)
__global__ void __launch_bounds__(256)
k_gemm(const float* __restrict__ A, int lda,
       const float* __restrict__ W, int ldw,
       const float* __restrict__ bias,
       float* __restrict__ C, int ldc,
       int K, int act, int cmode) {
    __shared__ float As[16 * 132];
    __shared__ float Ws[16 * 132];
    const int m0 = blockIdx.x * 128;
    const int n0 = blockIdx.y * 128;
    const int tx = threadIdx.x >> 4;   // n-group 0..15
    const int ty = threadIdx.x & 15;   // m-group 0..15
    const int lm = threadIdx.x >> 1;   // load row 0..127
    const int lq = (threadIdx.x & 1) * 8;

    ull acc[8][4];
    #pragma unroll
    for (int i = 0; i < 8; i++)
        #pragma unroll
        for (int j = 0; j < 4; j++) acc[i][j] = 0ull;

    for (int k0 = 0; k0 < K; k0 += 16) {
        float4 a0 = *reinterpret_cast<const float4*>(A + (size_t)(m0 + lm) * lda + k0 + lq);
        float4 a1 = *reinterpret_cast<const float4*>(A + (size_t)(m0 + lm) * lda + k0 + lq + 4);
        float4 w0 = *reinterpret_cast<const float4*>(W + (size_t)(n0 + lm) * ldw + k0 + lq);
        float4 w1 = *reinterpret_cast<const float4*>(W + (size_t)(n0 + lm) * ldw + k0 + lq + 4);
        __syncthreads();
        As[(lq + 0) * 132 + lm] = a0.x; As[(lq + 1) * 132 + lm] = a0.y;
        As[(lq + 2) * 132 + lm] = a0.z; As[(lq + 3) * 132 + lm] = a0.w;
        As[(lq + 4) * 132 + lm] = a1.x; As[(lq + 5) * 132 + lm] = a1.y;
        As[(lq + 6) * 132 + lm] = a1.z; As[(lq + 7) * 132 + lm] = a1.w;
        Ws[(lq + 0) * 132 + lm] = w0.x; Ws[(lq + 1) * 132 + lm] = w0.y;
        Ws[(lq + 2) * 132 + lm] = w0.z; Ws[(lq + 3) * 132 + lm] = w0.w;
        Ws[(lq + 4) * 132 + lm] = w1.x; Ws[(lq + 5) * 132 + lm] = w1.y;
        Ws[(lq + 6) * 132 + lm] = w1.z; Ws[(lq + 7) * 132 + lm] = w1.w;
        __syncthreads();
        #pragma unroll
        for (int k = 0; k < 16; k++) {
            float4 am0 = *reinterpret_cast<const float4*>(As + k * 132 + ty * 8);
            float4 am1 = *reinterpret_cast<const float4*>(As + k * 132 + ty * 8 + 4);
            ulonglong2 bn0 = *reinterpret_cast<const ulonglong2*>(Ws + k * 132 + tx * 8);
            ulonglong2 bn1 = *reinterpret_cast<const ulonglong2*>(Ws + k * 132 + tx * 8 + 4);
            float am[8] = {am0.x, am0.y, am0.z, am0.w, am1.x, am1.y, am1.z, am1.w};
            ull bp[4] = {bn0.x, bn0.y, bn1.x, bn1.y};
            #pragma unroll
            for (int mi = 0; mi < 8; mi++) {
                ull a2 = pack2(am[mi], am[mi]);
                #pragma unroll
                for (int np = 0; np < 4; np++) fma2(acc[mi][np], a2, bp[np]);
            }
        }
    }

    // epilogue
    float cv[8][8];
    #pragma unroll
    for (int mi = 0; mi < 8; mi++) {
        #pragma unroll
        for (int np = 0; np < 4; np++) {
            float2 p = unpack2(acc[mi][np]);
            float v0 = p.x + bias[n0 + tx * 8 + 2 * np];
            float v1 = p.y + bias[n0 + tx * 8 + 2 * np + 1];
            if (act == 1) { v0 = fmaxf(v0, 0.0f); v1 = fmaxf(v1, 0.0f); }
            cv[mi][2 * np] = v0; cv[mi][2 * np + 1] = v1;
        }
    }
    if (cmode == 0) {
        #pragma unroll
        for (int mi = 0; mi < 8; mi++) {
            int m = m0 + ty * 8 + mi;
            float4 s0 = make_float4(cv[mi][0], cv[mi][1], cv[mi][2], cv[mi][3]);
            float4 s1 = make_float4(cv[mi][4], cv[mi][5], cv[mi][6], cv[mi][7]);
            *reinterpret_cast<float4*>(C + (size_t)m * ldc + n0 + tx * 8)     = s0;
            *reinterpret_cast<float4*>(C + (size_t)m * ldc + n0 + tx * 8 + 4) = s1;
        }
    } else {
        const int t = blockIdx.x;          // m-tile == one full B
        #pragma unroll
        for (int j = 0; j < 8; j++) {
            int n = n0 + tx * 8 + j;
            float4 s0 = make_float4(cv[0][j], cv[1][j], cv[2][j], cv[3][j]);
            float4 s1 = make_float4(cv[4][j], cv[5][j], cv[6][j], cv[7][j]);
            size_t base = ((size_t)t * ldc + n) * B + ty * 8;
            *reinterpret_cast<float4*>(C + base)     = s0;
            *reinterpret_cast<float4*>(C + base + 4) = s1;
        }
    }
}

// ---------------- GEMM variant: A from transposed h [(t+1)][k][b] ----------------
__global__ void __launch_bounds__(256)
k_gemm_ht(const float* __restrict__ hT,
          const float* __restrict__ W, int ldw,
          const float* __restrict__ bias,
          float* __restrict__ C, int ldc,
          int K, int act) {
    __shared__ float As[16 * 132];
    __shared__ float Ws[16 * 132];
    const int m0 = blockIdx.x * 128;
    const int n0 = blockIdx.y * 128;
    const size_t slab = (size_t)(blockIdx.x + 1) * (H * B);
    const int tx = threadIdx.x >> 4;
    const int ty = threadIdx.x & 15;
    const int lm = threadIdx.x >> 1;
    const int lq = (threadIdx.x & 1) * 8;
    const int lk = threadIdx.x >> 4;       // k row for A load 0..15
    const int lb = (threadIdx.x & 15) * 8; // b offset for A load

    ull acc[8][4];
    #pragma unroll
    for (int i = 0; i < 8; i++)
        #pragma unroll
        for (int j = 0; j < 4; j++) acc[i][j] = 0ull;

    for (int k0 = 0; k0 < K; k0 += 16) {
        float4 h0 = *reinterpret_cast<const float4*>(hT + slab + (size_t)(k0 + lk) * B + lb);
        float4 h1 = *reinterpret_cast<const float4*>(hT + slab + (size_t)(k0 + lk) * B + lb + 4);
        float4 w0 = *reinterpret_cast<const float4*>(W + (size_t)(n0 + lm) * ldw + k0 + lq);
        float4 w1 = *reinterpret_cast<const float4*>(W + (size_t)(n0 + lm) * ldw + k0 + lq + 4);
        __syncthreads();
        *reinterpret_cast<float4*>(As + lk * 132 + lb)     = h0;
        *reinterpret_cast<float4*>(As + lk * 132 + lb + 4) = h1;
        Ws[(lq + 0) * 132 + lm] = w0.x; Ws[(lq + 1) * 132 + lm] = w0.y;
        Ws[(lq + 2) * 132 + lm] = w0.z; Ws[(lq + 3) * 132 + lm] = w0.w;
        Ws[(lq + 4) * 132 + lm] = w1.x; Ws[(lq + 5) * 132 + lm] = w1.y;
        Ws[(lq + 6) * 132 + lm] = w1.z; Ws[(lq + 7) * 132 + lm] = w1.w;
        __syncthreads();
        #pragma unroll
        for (int k = 0; k < 16; k++) {
            float4 am0 = *reinterpret_cast<const float4*>(As + k * 132 + ty * 8);
            float4 am1 = *reinterpret_cast<const float4*>(As + k * 132 + ty * 8 + 4);
            ulonglong2 bn0 = *reinterpret_cast<const ulonglong2*>(Ws + k * 132 + tx * 8);
            ulonglong2 bn1 = *reinterpret_cast<const ulonglong2*>(Ws + k * 132 + tx * 8 + 4);
            float am[8] = {am0.x, am0.y, am0.z, am0.w, am1.x, am1.y, am1.z, am1.w};
            ull bp[4] = {bn0.x, bn0.y, bn1.x, bn1.y};
            #pragma unroll
            for (int mi = 0; mi < 8; mi++) {
                ull a2 = pack2(am[mi], am[mi]);
                #pragma unroll
                for (int np = 0; np < 4; np++) fma2(acc[mi][np], a2, bp[np]);
            }
        }
    }
    #pragma unroll
    for (int mi = 0; mi < 8; mi++) {
        int m = m0 + ty * 8 + mi;
        float cv[8];
        #pragma unroll
        for (int np = 0; np < 4; np++) {
            float2 p = unpack2(acc[mi][np]);
            float v0 = p.x + bias[n0 + tx * 8 + 2 * np];
            float v1 = p.y + bias[n0 + tx * 8 + 2 * np + 1];
            if (act == 1) { v0 = fmaxf(v0, 0.0f); v1 = fmaxf(v1, 0.0f); }
            cv[2 * np] = v0; cv[2 * np + 1] = v1;
        }
        float4 s0 = make_float4(cv[0], cv[1], cv[2], cv[3]);
        float4 s1 = make_float4(cv[4], cv[5], cv[6], cv[7]);
        *reinterpret_cast<float4*>(C + (size_t)m * ldc + n0 + tx * 8)     = s0;
        *reinterpret_cast<float4*>(C + (size_t)m * ldc + n0 + tx * 8 + 4) = s1;
    }
}

// ---------------- persistent GRU scan ----------------
extern __shared__ float smem_dyn[];

__global__ void __launch_bounds__(SCAN_THREADS, 1)
k_gru_scan(const float* __restrict__ giT,  // [T][G][B]
           const float* __restrict__ Wh,   // [G, H]
           const float* __restrict__ bh,   // [G]
           float* __restrict__ hT)         // [(T+1), H, B]
{
    float* ws  = smem_dyn;                     // [512][12] : ws[k*12 + c], c = g*4+jj
    float* red = ws + 512 * 12;                // [16][12][128]
    float* sbh = red + SCAN_WARPS * 12 * 128;  // [12]
    const int tid  = threadIdx.x;
    const int warp = tid >> 5;
    const int lane = tid & 31;
    const int j0   = blockIdx.x * 4;

    for (int i = tid; i < 12 * 512; i += SCAN_THREADS) {
        int c = i >> 9, k = i & 511;
        ws[k * 12 + c] = Wh[((size_t)((c >> 2) * H + j0 + (c & 3))) * H + k];
    }
    if (tid < 12) sbh[tid] = bh[(tid >> 2) * H + j0 + (tid & 3)];
    __syncthreads();

    const int k0 = warp * 32;
    const int bbase = lane * 4;
    const int gjj = tid >> 7;       // gate-phase j
    const int gb  = tid & 127;      // gate-phase b
    const float bias_r = sbh[gjj];
    const float bias_z = sbh[4 + gjj];
    const float bias_n = sbh[8 + gjj];

    for (int t = 0; t < T; t++) {
        const float* hprev = hT + (size_t)t * (H * B);

        // prefetch gate-phase operands (coalesced; completes under the k-loop)
        size_t gibase = ((size_t)t * G + j0 + gjj) * B + gb;
        float ir  = giT[gibase];
        float iz  = giT[gibase + (size_t)H * B];
        float inn = giT[gibase + (size_t)2 * H * B];
        float hp  = hprev[(size_t)(j0 + gjj) * B + gb];

        ull acc[4][6];
        #pragma unroll
        for (int i = 0; i < 4; i++)
            #pragma unroll
            for (int cp = 0; cp < 6; cp++) acc[i][cp] = 0ull;

        #pragma unroll 4
        for (int kk = 0; kk < 32; kk++) {
            int k = k0 + kk;
            float4 hv = *reinterpret_cast<const float4*>(hprev + (size_t)k * B + bbase);
            ull h2[4];
            h2[0] = pack2(hv.x, hv.x);
            h2[1] = pack2(hv.y, hv.y);
            h2[2] = pack2(hv.z, hv.z);
            h2[3] = pack2(hv.w, hv.w);
            const float* wrow = ws + k * 12;
            ulonglong2 p0 = *reinterpret_cast<const ulonglong2*>(wrow);
            ulonglong2 p1 = *reinterpret_cast<const ulonglong2*>(wrow + 4);
            ulonglong2 p2 = *reinterpret_cast<const ulonglong2*>(wrow + 8);
            ull wp[6] = {p0.x, p0.y, p1.x, p1.y, p2.x, p2.y};
            #pragma unroll
            for (int cp = 0; cp < 6; cp++) {
                #pragma unroll
                for (int i = 0; i < 4; i++) fma2(acc[i][cp], h2[i], wp[cp]);
            }
        }

        #pragma unroll
        for (int cp = 0; cp < 6; cp++) {
            float2 v0 = unpack2(acc[0][cp]);
            float2 v1 = unpack2(acc[1][cp]);
            float2 v2 = unpack2(acc[2][cp]);
            float2 v3 = unpack2(acc[3][cp]);
            float4 a  = make_float4(v0.x, v1.x, v2.x, v3.x);
            float4 b4 = make_float4(v0.y, v1.y, v2.y, v3.y);
            *reinterpret_cast<float4*>(red + ((size_t)(warp * 12 + 2 * cp)) * B + bbase)     = a;
            *reinterpret_cast<float4*>(red + ((size_t)(warp * 12 + 2 * cp + 1)) * B + bbase) = b4;
        }
        __syncthreads();

        // gate phase: 512 outputs, one per thread
        {
            float gr = 0.f, gz = 0.f, gn = 0.f;
            #pragma unroll
            for (int w = 0; w < SCAN_WARPS; w++) {
                gr += red[(w * 12 + 0 + gjj) * B + gb];
                gz += red[(w * 12 + 4 + gjj) * B + gb];
                gn += red[(w * 12 + 8 + gjj) * B + gb];
            }
            float r = fsigmoid_(ir + gr + bias_r);
            float u = fsigmoid_(iz + gz + bias_z);
            float n = ftanh_(inn + r * (gn + bias_n));
            hT[((size_t)(t + 1) * H + j0 + gjj) * B + gb] = (1.0f - u) * n + u * hp;
        }

        grid_barrier();
    }
}

// ---------------- encoder output: zm, zs, z, planar flow ----------------
__global__ void k_flow_enc(const float* __restrict__ head,
                           const float* __restrict__ eps_enc,
                           const float* __restrict__ w_flow,
                           const float* __restrict__ b_flow,
                           const float* __restrict__ u_flow,
                           float* __restrict__ out,
                           float* __restrict__ z_all) {
    __shared__ float red[4][64];
    int rl = threadIdx.x >> 6;
    int j = threadIdx.x & 63;
    int row = blockIdx.x * 4 + rl;       // t*B + b
    int t = row >> 7;
    int b = row & 127;

    float zm = sigmoidf_(head[row * 128 + j]);
    float zs = softplusf_(head[row * 128 + 64 + j]);
    float eps = eps_enc[b * (T * Z) + t * Z + j];
    float z = eps * zs + zm;

    #pragma unroll
    for (int k = 0; k < KF; k++) {
        red[rl][j] = z * w_flow[(t * KF + k) * Z + j];
        __syncthreads();
        #pragma unroll
        for (int s = 32; s > 0; s >>= 1) {
            if (j < s) red[rl][j] += red[rl][j + s];
            __syncthreads();
        }
        float sv = red[rl][0] + b_flow[t * KF + k];
        __syncthreads();
        z += u_flow[(t * KF + k) * Z + j] * tanhf(sv);
    }

    int o = (b * T + t) * Z + j;
    out[2 + o]         = z;
    out[2 + S + o]     = zm;
    out[2 + 2 * S + o] = zs;
    z_all[row * Z + j] = z;
}

// ---------------- decoder output ----------------
__global__ void k_dec_out(const float* __restrict__ head,
                          const float* __restrict__ eps_dec,
                          float* __restrict__ out) {
    int i = blockIdx.x * blockDim.x + threadIdx.x;
    if (i >= S) return;
    int row = i >> 6;
    int j = i & 63;
    int t = row >> 7;
    int b = row & 127;
    float xm = sigmoidf_(head[row * 128 + j]);
    float xs = softplusf_(head[row * 128 + 64 + j]);
    float eps = eps_dec[b * (T * Xd) + t * Xd + j];
    float xo = eps * xs + xm;
    int o = (b * T + t) * Xd + j;
    out[2 + 3 * S + o] = xo;
    out[2 + 4 * S + o] = xm;
    out[2 + 5 * S + o] = xs;
}

// ---------------- deterministic two-pass reduction ----------------
__global__ void k_reduce_partial(const float* __restrict__ x,
                                 const float* __restrict__ out,
                                 double* __restrict__ part) {
    __shared__ double sn[256];
    __shared__ double sk[256];
    double accN = 0.0, accK = 0.0;
    for (int i = blockIdx.x * 256 + threadIdx.x; i < S; i += 256 * 256) {
        float zm = out[2 + S + i];
        float zs = out[2 + 2 * S + i];
        accK += 1.0 + (double)zs - (double)zm * zm - exp((double)zs);
        float xm = out[2 + 4 * S + i];
        float xs = out[2 + 5 * S + i];
        accK += 1.0 + (double)xs - (double)xm * xm - exp((double)xs);
        float xv = x[i];
        double d = ((double)xv - (double)xm) * exp(-0.5 * (double)xs);
        accN += (double)xs + d * d;
    }
    sn[threadIdx.x] = accN;
    sk[threadIdx.x] = accK;
    __syncthreads();
    for (int s = 128; s > 0; s >>= 1) {
        if (threadIdx.x < s) {
            sn[threadIdx.x] += sn[threadIdx.x + s];
            sk[threadIdx.x] += sk[threadIdx.x + s];
        }
        __syncthreads();
    }
    if (threadIdx.x == 0) {
        part[blockIdx.x * 2]     = sn[0];
        part[blockIdx.x * 2 + 1] = sk[0];
    }
}

__global__ void k_reduce_final(const double* __restrict__ part,
                               float* __restrict__ out) {
    __shared__ double sn[256];
    __shared__ double sk[256];
    sn[threadIdx.x] = part[threadIdx.x * 2];
    sk[threadIdx.x] = part[threadIdx.x * 2 + 1];
    __syncthreads();
    for (int s = 128; s > 0; s >>= 1) {
        if (threadIdx.x < s) {
            sn[threadIdx.x] += sn[threadIdx.x + s];
            sk[threadIdx.x] += sk[threadIdx.x + s];
        }
        __syncthreads();
    }
    if (threadIdx.x == 0) {
        out[0] = (float)(0.5 * sn[0]);
        out[1] = (float)(-0.5 * sk[0]);
    }
}

// ---------------- launch ----------------
extern "C" void kernel_launch(void* const* d_in, const int* in_sizes, int n_in,
                              void* d_out, int out_size) {
    const float* x        = (const float*)d_in[0];
    const float* eps_enc  = (const float*)d_in[1];
    const float* eps_dec  = (const float*)d_in[2];
    const float* Wi_enc   = (const float*)d_in[3];
    const float* Wh_enc   = (const float*)d_in[4];
    const float* bi_enc   = (const float*)d_in[5];
    const float* bh_enc   = (const float*)d_in[6];
    const float* Wphi_enc = (const float*)d_in[7];
    const float* bphi_enc = (const float*)d_in[8];
    const float* W_zmean  = (const float*)d_in[9];
    const float* b_zmean  = (const float*)d_in[10];
    const float* W_zstd   = (const float*)d_in[11];
    const float* b_zstd   = (const float*)d_in[12];
    const float* w_flow   = (const float*)d_in[13];
    const float* b_flow   = (const float*)d_in[14];
    const float* u_flow   = (const float*)d_in[15];
    const float* Wi_dec   = (const float*)d_in[16];
    const float* Wh_dec   = (const float*)d_in[17];
    const float* bi_dec   = (const float*)d_in[18];
    const float* bh_dec   = (const float*)d_in[19];
    const float* Wphi_dec = (const float*)d_in[20];
    const float* bphi_dec = (const float*)d_in[21];
    const float* W_xmean  = (const float*)d_in[22];
    const float* b_xmean  = (const float*)d_in[23];
    const float* W_xstd   = (const float*)d_in[24];
    const float* b_xstd   = (const float*)d_in[25];
    float* out = (float*)d_out;

    float *p_xT, *p_gi, *p_h, *p_phi, *p_head, *p_z, *p_Wh, *p_bh;
    double* p_part;
    cudaGetSymbolAddress((void**)&p_xT,   g_xT);
    cudaGetSymbolAddress((void**)&p_gi,   g_gi);
    cudaGetSymbolAddress((void**)&p_h,    g_h);
    cudaGetSymbolAddress((void**)&p_phi,  g_phi);
    cudaGetSymbolAddress((void**)&p_head, g_head);
    cudaGetSymbolAddress((void**)&p_z,    g_z);
    cudaGetSymbolAddress((void**)&p_Wh,   g_Whead);
    cudaGetSymbolAddress((void**)&p_bh,   g_bhead);
    cudaGetSymbolAddress((void**)&p_part, g_part);

    cudaFuncSetAttribute(k_gru_scan, cudaFuncAttributeMaxDynamicSharedMemorySize, SCAN_SMEM);

    // 0) rearrange x, zero h slab 0
    k_transpose_x<<<(B * T * Xd + 255) / 256, 256>>>(x, p_xT);
    k_zero<<<(H * B + 255) / 256, 256>>>(p_h, H * B);

    // 1) gi_enc = xT @ Wi_enc.T + bi_enc -> transposed [t][col][b]
    {
        dim3 grid(BT / 128, G / 128);
        k_gemm<<<grid, 256>>>(p_xT, Xd, Wi_enc, Xd, bi_enc, p_gi, G, Xd, 0, 1);
    }
    // 2) encoder GRU scan (persistent)
    k_gru_scan<<<NBLK, SCAN_THREADS, SCAN_SMEM>>>(p_gi, Wh_enc, bh_enc, p_h);

    // 3) phi_enc = relu(h_all @ Wphi_enc[:, :H].T + b)
    {
        dim3 grid(BT / 128, D / 128);
        k_gemm_ht<<<grid, 256>>>(p_h, Wphi_enc, H + Z, bphi_enc, p_phi, D, H, 1);
    }
    // 4) z heads (fused into one N=128 GEMM)
    k_pack_head<<<128, 256>>>(W_zmean, b_zmean, W_zstd, b_zstd, p_Wh, p_bh);
    {
        dim3 grid(BT / 128, 1);
        k_gemm<<<grid, 256>>>(p_phi, D, p_Wh, D, p_bh, p_head, 128, D, 0, 0);
    }
    // 5) flow + z outputs
    k_flow_enc<<<BT / 4, 256>>>(p_head, eps_enc, w_flow, b_flow, u_flow, out, p_z);

    // 6) gi_dec = z_all @ Wi_dec.T + bi_dec -> transposed
    {
        dim3 grid(BT / 128, G / 128);
        k_gemm<<<grid, 256>>>(p_z, Z, Wi_dec, Z, bi_dec, p_gi, G, Z, 0, 1);
    }
    // 7) decoder GRU scan (h slab 0 still zero)
    k_gru_scan<<<NBLK, SCAN_THREADS, SCAN_SMEM>>>(p_gi, Wh_dec, bh_dec, p_h);

    // 8) phi_dec
    {
        dim3 grid(BT / 128, D / 128);
        k_gemm_ht<<<grid, 256>>>(p_h, Wphi_dec, H, bphi_dec, p_phi, D, H, 1);
    }
    // 9) x heads (fused)
    k_pack_head<<<128, 256>>>(W_xmean, b_xmean, W_xstd, b_xstd, p_Wh, p_bh);
    {
        dim3 grid(BT / 128, 1);
        k_gemm<<<grid, 256>>>(p_phi, D, p_Wh, D, p_bh, p_head, 128, D, 0, 0);
    }
    // 10) decoder outputs
    k_dec_out<<<(S + 255) / 256, 256>>>(p_head, eps_dec, out);

    // 11) reductions
    k_reduce_partial<<<256, 256>>>(x, out, p_part);
    k_reduce_final<<<1, 256>>>(p_part, out);
}